// round 12
// baseline (speedup 1.0000x reference)
#include <cuda_runtime.h>
#include <math.h>

// Problem constants (shapes fixed by setup_inputs)
#define C_DIM   20
#define C2      10          // channel pairs
#define HW      524288      // 512*1024
#define HW4     131072      // HW/4 (float4 units)
#define HW4_SH  17          // log2(HW4)
#define BLK     512

__device__ __forceinline__ float sqrt_approx(float v) {
    float r; asm("sqrt.approx.f32 %0, %1;" : "=f"(r) : "f"(v)); return r;
}
__device__ __forceinline__ float rsqrt_approx(float v) {
    float r; asm("rsqrt.approx.f32 %0, %1;" : "=f"(r) : "f"(v)); return r;
}
// packed fp32x2 FMA: d = a*b + d   (FFMA2 — only reachable via PTX)
__device__ __forceinline__ void ffma2(unsigned long long& d,
                                      unsigned long long a,
                                      unsigned long long b) {
    asm("fma.rn.f32x2 %0, %1, %2, %0;" : "+l"(d) : "l"(a), "l"(b));
}
__device__ __forceinline__ unsigned long long pack2(float lo, float hi) {
    unsigned long long r;
    asm("mov.b64 %0, {%1, %2};" : "=l"(r) : "f"(lo), "f"(hi));
    return r;
}
__device__ __forceinline__ void unpack2(float& lo, float& hi, unsigned long long v) {
    asm("mov.b64 {%0, %1}, %2;" : "=f"(lo), "=f"(hi) : "l"(v));
}

// ---------------------------------------------------------------------------
// Single fused kernel (R3 compute core, 512-thread CTAs => one CTA per SM,
// contiguous 8KB per plane per CTA for better DRAM row locality):
//  - All threads issue their 20 feature LDG.128 FIRST (deep MLP burst).
//  - While those loads fly, threads 0..19 redundantly normalize the 20x20
//    prototype matrix into smem.
//  - __syncthreads, then channel-pair packing + FFMA2 dot products against
//    smem prototype rows (LDS.128 broadcast, 5 per row); STG.128 stores
//    spread across the m-loop.
//   input  float4 idx: b*C*HW4 + c*HW4 + rem
//   output float4 idx: b*C*HW4 + m*HW4 + rem
// ---------------------------------------------------------------------------
__global__ __launch_bounds__(BLK, 1)
void isomax_dist_kernel(const float* __restrict__ in,
                        const float* __restrict__ protos,
                        const float* __restrict__ scale_p,
                        float* __restrict__ out) {
    __shared__ float sp[C_DIM * C_DIM];   // normalized proto rows (80B = 5x16B)
    __shared__ float spsn[C_DIM];         // ||p_hat||^2 per row

    const float4* __restrict__ in4  = (const float4*)in;
    float4*       __restrict__ out4 = (float4*)out;

    unsigned q   = blockIdx.x * BLK + threadIdx.x;   // global float4-pixel index
    unsigned b   = q >> HW4_SH;
    unsigned rem = q & (HW4 - 1u);
    unsigned base4 = b * (C_DIM * HW4) + rem;

    // ---- Phase 1: issue the 20 feature loads (they fly during proto prep) ----
    float4 raw[C_DIM];
    #pragma unroll
    for (int c = 0; c < C_DIM; c++)
        raw[c] = in4[base4 + (unsigned)c * HW4];

    // ---- Phase 2: per-CTA prototype normalization (hidden under load latency) ----
    if (threadIdx.x < C_DIM) {
        int m = threadIdx.x;
        float v[C_DIM];
        float sq = 0.f;
        #pragma unroll
        for (int c = 0; c < C_DIM; c++) {
            v[c] = __ldg(&protos[m * C_DIM + c]);
            sq = fmaf(v[c], v[c], sq);
        }
        float inv = 1.0f / fmaxf(sqrtf(sq), 1e-12f);
        float s = 0.f;
        #pragma unroll
        for (int c = 0; c < C_DIM; c++) {
            float pv = v[c] * inv;
            sp[m * C_DIM + c] = pv;
            s = fmaf(pv, pv, s);
        }
        spsn[m] = s;
    }
    const float sneg = -fabsf(__ldg(scale_p));   // logits = -|scale| * dist
    __syncthreads();

    // ---- Phase 3: pack along channel pairs + squared-norm accumulation ----
    unsigned long long xp[C2 * 4];
    unsigned long long xsq2[4] = {0ull, 0ull, 0ull, 0ull};
    #pragma unroll
    for (int c2 = 0; c2 < C2; c2++) {
        float4 a  = raw[2 * c2];
        float4 b4 = raw[2 * c2 + 1];
        unsigned long long p0 = pack2(a.x, b4.x);
        unsigned long long p1 = pack2(a.y, b4.y);
        unsigned long long p2 = pack2(a.z, b4.z);
        unsigned long long p3 = pack2(a.w, b4.w);
        xp[c2 * 4 + 0] = p0; ffma2(xsq2[0], p0, p0);
        xp[c2 * 4 + 1] = p1; ffma2(xsq2[1], p1, p1);
        xp[c2 * 4 + 2] = p2; ffma2(xsq2[2], p2, p2);
        xp[c2 * 4 + 3] = p3; ffma2(xsq2[3], p3, p3);
    }

    // Per-pixel: inv = 1/||x|| (rsqrt, clamped), xn = ||x_hat||^2, n2i = -2*inv
    float xn[4], n2i[4];
    #pragma unroll
    for (int j = 0; j < 4; j++) {
        float lo, hi;
        unpack2(lo, hi, xsq2[j]);
        float xsq = lo + hi;
        float inv = rsqrt_approx(fmaxf(xsq, 1e-24f));
        xn[j]  = xsq * inv * inv;
        n2i[j] = -2.f * inv;
    }

    // ---- Phase 4: 20 dot products + distance epilogue + spread stores ----
    #pragma unroll 1
    for (int m = 0; m < C_DIM; m++) {
        // prototype row m as 5 x ulonglong2 (each = 2 channel pairs), LDS.128
        const ulonglong2* pr = (const ulonglong2*)&sp[m * C_DIM];
        unsigned long long acc[4] = {0ull, 0ull, 0ull, 0ull};
        #pragma unroll
        for (int c4 = 0; c4 < C2 / 2; c4++) {
            ulonglong2 pp = pr[c4];
            ffma2(acc[0], xp[(2 * c4) * 4 + 0], pp.x);
            ffma2(acc[1], xp[(2 * c4) * 4 + 1], pp.x);
            ffma2(acc[2], xp[(2 * c4) * 4 + 2], pp.x);
            ffma2(acc[3], xp[(2 * c4) * 4 + 3], pp.x);
            ffma2(acc[0], xp[(2 * c4 + 1) * 4 + 0], pp.y);
            ffma2(acc[1], xp[(2 * c4 + 1) * 4 + 1], pp.y);
            ffma2(acc[2], xp[(2 * c4 + 1) * 4 + 2], pp.y);
            ffma2(acc[3], xp[(2 * c4 + 1) * 4 + 3], pp.y);
        }
        float psn = spsn[m];

        float4 o;
        #pragma unroll
        for (int j = 0; j < 4; j++) {
            float lo, hi;
            unpack2(lo, hi, acc[j]);
            float dot = lo + hi;
            float d2 = fmaf(dot, n2i[j], xn[j] + psn);
            d2 = fmaxf(d2, 0.f);
            ((float*)&o)[j] = sneg * sqrt_approx(d2);
        }
        out4[base4 + (unsigned)m * HW4] = o;
    }
}

extern "C" void kernel_launch(void* const* d_in, const int* in_sizes, int n_in,
                              void* d_out, int out_size) {
    const float* features = (const float*)d_in[0];  // [8,20,512,1024] f32
    const float* protos   = (const float*)d_in[1];  // [20,20] f32
    const float* dscale   = (const float*)d_in[2];  // [1] f32

    int n_pix4 = (in_sizes[0] / C_DIM) / 4;         // float4 pixel groups
    int grid = (n_pix4 + BLK - 1) / BLK;            // 2048, exact coverage
    isomax_dist_kernel<<<grid, BLK>>>(features, protos, dscale, (float*)d_out);
}

// round 13
// speedup vs baseline: 1.2806x; 1.2806x over previous
#include <cuda_runtime.h>
#include <math.h>

// Problem constants (shapes fixed by setup_inputs)
#define C_DIM   20
#define C2      10          // channel pairs
#define HW      524288      // 512*1024
#define HW4     131072      // HW/4 (float4 units)
#define HW4_SH  17          // log2(HW4)
#define BLK     128

__device__ __forceinline__ float sqrt_approx(float v) {
    float r; asm("sqrt.approx.f32 %0, %1;" : "=f"(r) : "f"(v)); return r;
}
__device__ __forceinline__ float rsqrt_approx(float v) {
    float r; asm("rsqrt.approx.f32 %0, %1;" : "=f"(r) : "f"(v)); return r;
}
// packed fp32x2 FMA: d = a*b + d   (FFMA2 — only reachable via PTX)
__device__ __forceinline__ void ffma2(unsigned long long& d,
                                      unsigned long long a,
                                      unsigned long long b) {
    asm("fma.rn.f32x2 %0, %1, %2, %0;" : "+l"(d) : "l"(a), "l"(b));
}
__device__ __forceinline__ unsigned long long pack2(float lo, float hi) {
    unsigned long long r;
    asm("mov.b64 %0, {%1, %2};" : "=l"(r) : "f"(lo), "f"(hi));
    return r;
}
__device__ __forceinline__ void unpack2(float& lo, float& hi, unsigned long long v) {
    asm("mov.b64 {%0, %1}, %2;" : "=f"(lo), "=f"(hi) : "l"(v));
}

// ---------------------------------------------------------------------------
// Single fused kernel (R9 compute core, 128-thread CTAs => 4 independent
// CTAs per SM: four decorrelated load/compute/store phase clocks per SM so
// reads from one CTA overlay stores from another):
//  - All threads issue their 20 feature LDG.128 FIRST (deep MLP burst).
//  - While those loads fly, threads 0..19 redundantly normalize the 20x20
//    prototype matrix into smem.
//  - __syncthreads, then channel-pair packing + FFMA2 dot products against
//    smem prototype rows (LDS.128 broadcast, 5 per row); STG.128 stores
//    spread across the m-loop.
//   input  float4 idx: b*C*HW4 + c*HW4 + rem
//   output float4 idx: b*C*HW4 + m*HW4 + rem
// ---------------------------------------------------------------------------
__global__ __launch_bounds__(BLK, 4)
void isomax_dist_kernel(const float* __restrict__ in,
                        const float* __restrict__ protos,
                        const float* __restrict__ scale_p,
                        float* __restrict__ out) {
    __shared__ float sp[C_DIM * C_DIM];   // normalized proto rows (80B = 5x16B)
    __shared__ float spsn[C_DIM];         // ||p_hat||^2 per row

    const float4* __restrict__ in4  = (const float4*)in;
    float4*       __restrict__ out4 = (float4*)out;

    unsigned q   = blockIdx.x * BLK + threadIdx.x;   // global float4-pixel index
    unsigned b   = q >> HW4_SH;
    unsigned rem = q & (HW4 - 1u);
    unsigned base4 = b * (C_DIM * HW4) + rem;

    // ---- Phase 1: issue the 20 feature loads (they fly during proto prep) ----
    float4 raw[C_DIM];
    #pragma unroll
    for (int c = 0; c < C_DIM; c++)
        raw[c] = in4[base4 + (unsigned)c * HW4];

    // ---- Phase 2: per-CTA prototype normalization (hidden under load latency) ----
    if (threadIdx.x < C_DIM) {
        int m = threadIdx.x;
        float v[C_DIM];
        float sq = 0.f;
        #pragma unroll
        for (int c = 0; c < C_DIM; c++) {
            v[c] = __ldg(&protos[m * C_DIM + c]);
            sq = fmaf(v[c], v[c], sq);
        }
        float inv = 1.0f / fmaxf(sqrtf(sq), 1e-12f);
        float s = 0.f;
        #pragma unroll
        for (int c = 0; c < C_DIM; c++) {
            float pv = v[c] * inv;
            sp[m * C_DIM + c] = pv;
            s = fmaf(pv, pv, s);
        }
        spsn[m] = s;
    }
    const float sneg = -fabsf(__ldg(scale_p));   // logits = -|scale| * dist
    __syncthreads();

    // ---- Phase 3: pack along channel pairs + squared-norm accumulation ----
    unsigned long long xp[C2 * 4];
    unsigned long long xsq2[4] = {0ull, 0ull, 0ull, 0ull};
    #pragma unroll
    for (int c2 = 0; c2 < C2; c2++) {
        float4 a  = raw[2 * c2];
        float4 b4 = raw[2 * c2 + 1];
        unsigned long long p0 = pack2(a.x, b4.x);
        unsigned long long p1 = pack2(a.y, b4.y);
        unsigned long long p2 = pack2(a.z, b4.z);
        unsigned long long p3 = pack2(a.w, b4.w);
        xp[c2 * 4 + 0] = p0; ffma2(xsq2[0], p0, p0);
        xp[c2 * 4 + 1] = p1; ffma2(xsq2[1], p1, p1);
        xp[c2 * 4 + 2] = p2; ffma2(xsq2[2], p2, p2);
        xp[c2 * 4 + 3] = p3; ffma2(xsq2[3], p3, p3);
    }

    // Per-pixel: inv = 1/||x|| (rsqrt, clamped), xn = ||x_hat||^2, n2i = -2*inv
    float xn[4], n2i[4];
    #pragma unroll
    for (int j = 0; j < 4; j++) {
        float lo, hi;
        unpack2(lo, hi, xsq2[j]);
        float xsq = lo + hi;
        float inv = rsqrt_approx(fmaxf(xsq, 1e-24f));
        xn[j]  = xsq * inv * inv;
        n2i[j] = -2.f * inv;
    }

    // ---- Phase 4: 20 dot products + distance epilogue + spread stores ----
    #pragma unroll 1
    for (int m = 0; m < C_DIM; m++) {
        // prototype row m as 5 x ulonglong2 (each = 2 channel pairs), LDS.128
        const ulonglong2* pr = (const ulonglong2*)&sp[m * C_DIM];
        unsigned long long acc[4] = {0ull, 0ull, 0ull, 0ull};
        #pragma unroll
        for (int c4 = 0; c4 < C2 / 2; c4++) {
            ulonglong2 pp = pr[c4];
            ffma2(acc[0], xp[(2 * c4) * 4 + 0], pp.x);
            ffma2(acc[1], xp[(2 * c4) * 4 + 1], pp.x);
            ffma2(acc[2], xp[(2 * c4) * 4 + 2], pp.x);
            ffma2(acc[3], xp[(2 * c4) * 4 + 3], pp.x);
            ffma2(acc[0], xp[(2 * c4 + 1) * 4 + 0], pp.y);
            ffma2(acc[1], xp[(2 * c4 + 1) * 4 + 1], pp.y);
            ffma2(acc[2], xp[(2 * c4 + 1) * 4 + 2], pp.y);
            ffma2(acc[3], xp[(2 * c4 + 1) * 4 + 3], pp.y);
        }
        float psn = spsn[m];

        float4 o;
        #pragma unroll
        for (int j = 0; j < 4; j++) {
            float lo, hi;
            unpack2(lo, hi, acc[j]);
            float dot = lo + hi;
            float d2 = fmaf(dot, n2i[j], xn[j] + psn);
            d2 = fmaxf(d2, 0.f);
            ((float*)&o)[j] = sneg * sqrt_approx(d2);
        }
        out4[base4 + (unsigned)m * HW4] = o;
    }
}

extern "C" void kernel_launch(void* const* d_in, const int* in_sizes, int n_in,
                              void* d_out, int out_size) {
    const float* features = (const float*)d_in[0];  // [8,20,512,1024] f32
    const float* protos   = (const float*)d_in[1];  // [20,20] f32
    const float* dscale   = (const float*)d_in[2];  // [1] f32

    int n_pix4 = (in_sizes[0] / C_DIM) / 4;         // float4 pixel groups
    int grid = (n_pix4 + BLK - 1) / BLK;            // 8192, exact coverage
    isomax_dist_kernel<<<grid, BLK>>>(features, protos, dscale, (float*)d_out);
}